// round 8
// baseline (speedup 1.0000x reference)
#include <cuda_runtime.h>

// RoIPooling2D (Caffe roi_pool, max) — NHWC gather, direct-store version.
// x [B=2,C=256,H=50,W=50] f32, rois [N,5], out [N,256,7,7] f32.
// Bounds replicate XLA:GPU arithmetic exactly (div.full.f32, proven Round 3).
//
//   1) transpose_in: x NCHW -> g_xt NHWC ([b][h*w][c])
//   2) gather: grid (N, 2 ch-halves, 2 bin-groups) = 512 blocks, 512 thr.
//      lane = 4 channels (float4), warp = bin. Per-row 4-wide predicated
//      load batch (MLP=4, 16 regs). Results stored DIRECTLY to gmem as 4
//      scalar STG per lane — no smem staging, no second barrier (same L1
//      store-wavefront count as the staged float4 path, ~1600 fewer instrs).

#define POOL_H 7
#define POOL_W 7
#define NBINS  (POOL_H * POOL_W)       // 49
#define SPATIAL_SCALE 0.0625f
#define C_TOT  256
#define HDIM   50
#define WDIM   50
#define HW     (HDIM * WDIM)           // 2500
#define CH     128                     // channels per gather block
#define NB0    25
#define NB1    24
#define GTHREADS 512
#define NWARPS (GTHREADS / 32)
#define NEG_FLT_MAX (-3.402823466e38f)

__device__ float g_xt[2 * HW * C_TOT];  // NHWC scratch, 5.12 MB

__device__ __forceinline__ float div_full(float a, float b) {
    float r;
    asm("div.full.f32 %0, %1, %2;" : "=f"(r) : "f"(a), "f"(b));
    return r;
}

__device__ __forceinline__ float4 fmax4(float4 a, float4 b) {
    return make_float4(fmaxf(a.x, b.x), fmaxf(a.y, b.y),
                       fmaxf(a.z, b.z), fmaxf(a.w, b.w));
}

// ---------------- Kernel 1: NCHW -> NHWC transpose ----------------
__global__ void transpose_in_kernel(const float* __restrict__ x) {
    __shared__ float tile[32][33];
    int b  = blockIdx.z;
    int p0 = blockIdx.x * 32;
    int c0 = blockIdx.y * 32;
    int tx = threadIdx.x;
    int ty = threadIdx.y;

    #pragma unroll
    for (int k = 0; k < 4; ++k) {
        int c = c0 + ty + k * 8;
        int p = p0 + tx;
        if (p < HW)
            tile[ty + k * 8][tx] = x[((size_t)b * C_TOT + c) * HW + p];
    }
    __syncthreads();
    #pragma unroll
    for (int k = 0; k < 4; ++k) {
        int p = p0 + ty + k * 8;
        int c = c0 + tx;
        if (p < HW)
            g_xt[((size_t)b * HW + p) * C_TOT + c] = tile[tx][ty + k * 8];
    }
}

// ---------------- Kernel 2: fused bounds + gather + direct store ----------------
__global__ void __launch_bounds__(GTHREADS)
roi_gather_kernel(const float* __restrict__ rois, float* __restrict__ out, int N) {
    __shared__ int s_hs[POOL_H], s_he[POOL_H], s_ws[POOL_W], s_we[POOL_W];
    __shared__ int s_b;

    int n    = blockIdx.x;
    int half = blockIdx.y;                 // channel half
    int grp  = blockIdx.z;                 // bin group: 0 -> [0,25), 1 -> [25,49)
    int bin0 = grp ? NB0 : 0;
    int nb   = grp ? NB1 : NB0;
    int tid  = threadIdx.x;
    int warp = tid >> 5;
    int lane = tid & 31;

    // --- bounds (exact replica of reference arithmetic, incl. div.full) ---
    if (tid < POOL_H + POOL_W + 1) {
        const float* r = rois + n * 5;
        if (tid == POOL_H + POOL_W) {
            s_b = (int)r[0];
        } else {
            bool is_h = (tid < POOL_H);
            int  i    = is_h ? tid : tid - POOL_H;
            float s1  = rintf(__fmul_rn(r[is_h ? 2 : 1], SPATIAL_SCALE));
            float e1  = rintf(__fmul_rn(r[is_h ? 4 : 3], SPATIAL_SCALE));
            float sz  = fmaxf(__fadd_rn(__fsub_rn(e1, s1), 1.0f), 1.0f);
            float bs  = div_full(sz, is_h ? (float)POOL_H : (float)POOL_W);
            float npx = is_h ? (float)HDIM : (float)WDIM;
            float lo = __fadd_rn(floorf(__fmul_rn((float)i, bs)), s1);
            float hi = __fadd_rn(ceilf(__fmul_rn((float)(i + 1), bs)), s1);
            lo = fminf(fmaxf(lo, 0.0f), npx);
            hi = fminf(fmaxf(hi, 0.0f), npx);
            if (is_h) { s_hs[i] = (int)lo; s_he[i] = (int)hi; }
            else      { s_ws[i] = (int)lo; s_we[i] = (int)hi; }
        }
    }
    __syncthreads();

    // --- gather: warp = bin (within group), lane = 4 channels (float4) ---
    int c4 = half * CH + lane * 4;                 // lane's first global channel
    const float* xb = g_xt + (size_t)s_b * (HW * C_TOT) + c4;
    // lane's output row: out[n][c4][*]
    float* ob = out + (size_t)n * (C_TOT * NBINS) + (size_t)c4 * NBINS;

    for (int bl = warp; bl < nb; bl += NWARPS) {
        int bin = bin0 + bl;
        int ph = bin / POOL_W;
        int pw = bin - ph * POOL_W;
        int hs = s_hs[ph], he = s_he[ph];
        int ws = s_ws[pw], we = s_we[pw];
        int ww = we - ws;
        bool empty = (he <= hs) || (ww <= 0);

        float4 m = make_float4(NEG_FLT_MAX, NEG_FLT_MAX, NEG_FLT_MAX, NEG_FLT_MAX);
        if (!empty) {
            const float* rowp = xb + (size_t)(hs * WDIM) * C_TOT + (size_t)ws * C_TOT;
            if (ww <= 4) {
                bool p1 = ww > 1, p2 = ww > 2, p3 = ww > 3;
                for (int h = hs; h < he; ++h) {
                    // 4 independent predicated loads in flight, then fold.
                    float4 a0, a1, a2, a3;
                    a0 = __ldg(reinterpret_cast<const float4*>(rowp));
                    if (p1) a1 = __ldg(reinterpret_cast<const float4*>(rowp + C_TOT));
                    if (p2) a2 = __ldg(reinterpret_cast<const float4*>(rowp + 2 * C_TOT));
                    if (p3) a3 = __ldg(reinterpret_cast<const float4*>(rowp + 3 * C_TOT));
                    m = fmax4(m, a0);
                    if (p1) m = fmax4(m, a1);
                    if (p2) m = fmax4(m, a2);
                    if (p3) m = fmax4(m, a3);
                    rowp += WDIM * C_TOT;
                }
            } else {
                // Fallback (never hit with this data shape, kept for safety).
                for (int h = hs; h < he; ++h) {
                    const float* q = rowp;
                    for (int w = 0; w < ww; ++w) {
                        m = fmax4(m, __ldg(reinterpret_cast<const float4*>(q)));
                        q += C_TOT;
                    }
                    rowp += WDIM * C_TOT;
                }
            }
        } else {
            m = make_float4(0.f, 0.f, 0.f, 0.f);
        }

        // Direct scattered store: 4 channels, stride NBINS floats.
        ob[0 * NBINS + bin] = m.x;
        ob[1 * NBINS + bin] = m.y;
        ob[2 * NBINS + bin] = m.z;
        ob[3 * NBINS + bin] = m.w;
    }
}

extern "C" void kernel_launch(void* const* d_in, const int* in_sizes, int n_in,
                              void* d_out, int out_size) {
    const float* x    = (const float*)d_in[0];   // [B,256,50,50]
    const float* rois = (const float*)d_in[1];   // [N,5]
    float* out = (float*)d_out;                  // [N,256,7,7]

    const int N = in_sizes[1] / 5;
    const int B = in_sizes[0] / (C_TOT * HW);

    dim3 tgrid((HW + 31) / 32, C_TOT / 32, B);
    dim3 tblock(32, 8);
    transpose_in_kernel<<<tgrid, tblock>>>(x);

    dim3 ggrid(N, C_TOT / CH, 2);                // (128, 2, 2) = 512 blocks
    roi_gather_kernel<<<ggrid, GTHREADS>>>(rois, out, N);
}

// round 9
// speedup vs baseline: 1.2542x; 1.2542x over previous
#include <cuda_runtime.h>

// RoIPooling2D (Caffe roi_pool, max) — NHWC gather.
// R7 structure (bin-split grid, smem staging, const-div write) with R8's
// spill-free 4-wide predicated load batch (MLP=4) as the inner loop.
// Bounds replicate XLA:GPU arithmetic exactly (div.full.f32, proven Round 3).

#define POOL_H 7
#define POOL_W 7
#define NBINS  (POOL_H * POOL_W)       // 49
#define SPATIAL_SCALE 0.0625f
#define C_TOT  256
#define HDIM   50
#define WDIM   50
#define HW     (HDIM * WDIM)           // 2500
#define CH     128                     // channels per gather block
#define NB0    25
#define NB1    24
#define GTHREADS 512
#define NWARPS (GTHREADS / 32)
#define NEG_FLT_MAX (-3.402823466e38f)

__device__ float g_xt[2 * HW * C_TOT];  // NHWC scratch, 5.12 MB

__device__ __forceinline__ float div_full(float a, float b) {
    float r;
    asm("div.full.f32 %0, %1, %2;" : "=f"(r) : "f"(a), "f"(b));
    return r;
}

__device__ __forceinline__ float4 fmax4(float4 a, float4 b) {
    return make_float4(fmaxf(a.x, b.x), fmaxf(a.y, b.y),
                       fmaxf(a.z, b.z), fmaxf(a.w, b.w));
}

// ---------------- Kernel 1: NCHW -> NHWC transpose ----------------
__global__ void transpose_in_kernel(const float* __restrict__ x) {
    __shared__ float tile[32][33];
    int b  = blockIdx.z;
    int p0 = blockIdx.x * 32;
    int c0 = blockIdx.y * 32;
    int tx = threadIdx.x;
    int ty = threadIdx.y;

    #pragma unroll
    for (int k = 0; k < 4; ++k) {
        int c = c0 + ty + k * 8;
        int p = p0 + tx;
        if (p < HW)
            tile[ty + k * 8][tx] = x[((size_t)b * C_TOT + c) * HW + p];
    }
    __syncthreads();
    #pragma unroll
    for (int k = 0; k < 4; ++k) {
        int p = p0 + ty + k * 8;
        int c = c0 + tx;
        if (p < HW)
            g_xt[((size_t)b * HW + p) * C_TOT + c] = tile[tx][ty + k * 8];
    }
}

// Constant-NB write: division by compile-time constant -> mulhi, coalesced.
template <int NB>
__device__ __forceinline__ void write_out(float* __restrict__ obase,
                                          const float* __restrict__ s_res,
                                          int tid) {
    const int total = CH * NB;
    for (int i = tid; i < total; i += GTHREADS) {
        int c = i / NB;
        int j = i - c * NB;
        obase[c * NBINS + j] = s_res[c * NB0 + j];
    }
}

// ---------------- Kernel 2: fused bounds + MLP-4 gather ----------------
__global__ void __launch_bounds__(GTHREADS)
roi_gather_kernel(const float* __restrict__ rois, float* __restrict__ out, int N) {
    __shared__ float s_res[CH * NB0];   // [c_local][bin_local], 12.8 KB
    __shared__ int   s_hs[POOL_H], s_he[POOL_H], s_ws[POOL_W], s_we[POOL_W];
    __shared__ int   s_b;

    int n    = blockIdx.x;
    int half = blockIdx.y;                 // channel half
    int grp  = blockIdx.z;                 // bin group: 0 -> [0,25), 1 -> [25,49)
    int bin0 = grp ? NB0 : 0;
    int nb   = grp ? NB1 : NB0;
    int tid  = threadIdx.x;
    int warp = tid >> 5;
    int lane = tid & 31;

    // --- bounds (exact replica of reference arithmetic, incl. div.full) ---
    if (tid < POOL_H + POOL_W + 1) {
        const float* r = rois + n * 5;
        if (tid == POOL_H + POOL_W) {
            s_b = (int)r[0];
        } else {
            bool is_h = (tid < POOL_H);
            int  i    = is_h ? tid : tid - POOL_H;
            float s1  = rintf(__fmul_rn(r[is_h ? 2 : 1], SPATIAL_SCALE));
            float e1  = rintf(__fmul_rn(r[is_h ? 4 : 3], SPATIAL_SCALE));
            float sz  = fmaxf(__fadd_rn(__fsub_rn(e1, s1), 1.0f), 1.0f);
            float bs  = div_full(sz, is_h ? (float)POOL_H : (float)POOL_W);
            float npx = is_h ? (float)HDIM : (float)WDIM;
            float lo = __fadd_rn(floorf(__fmul_rn((float)i, bs)), s1);
            float hi = __fadd_rn(ceilf(__fmul_rn((float)(i + 1), bs)), s1);
            lo = fminf(fmaxf(lo, 0.0f), npx);
            hi = fminf(fmaxf(hi, 0.0f), npx);
            if (is_h) { s_hs[i] = (int)lo; s_he[i] = (int)hi; }
            else      { s_ws[i] = (int)lo; s_we[i] = (int)hi; }
        }
    }
    __syncthreads();

    // --- gather: warp = bin (within group), lane = 4 channels (float4) ---
    int c4 = half * CH + lane * 4;
    const float* xb = g_xt + (size_t)s_b * (HW * C_TOT) + c4;

    for (int bl = warp; bl < nb; bl += NWARPS) {
        int bin = bin0 + bl;
        int ph = bin / POOL_W;
        int pw = bin - ph * POOL_W;
        int hs = s_hs[ph], he = s_he[ph];
        int ws = s_ws[pw], we = s_we[pw];
        int ww = we - ws;
        bool empty = (he <= hs) || (ww <= 0);

        float4 m = make_float4(NEG_FLT_MAX, NEG_FLT_MAX, NEG_FLT_MAX, NEG_FLT_MAX);
        if (!empty) {
            const float* rowp = xb + ((size_t)(hs * WDIM) + ws) * C_TOT;
            if (ww <= 4) {
                bool p1 = ww > 1, p2 = ww > 2, p3 = ww > 3;
                for (int h = hs; h < he; ++h) {
                    // 4 independent predicated float4 loads in flight (MLP=4),
                    // named scalars (no arrays) -> no spill (proven R8, regs=50).
                    float4 a0, a1, a2, a3;
                    a0 = __ldg(reinterpret_cast<const float4*>(rowp));
                    if (p1) a1 = __ldg(reinterpret_cast<const float4*>(rowp + C_TOT));
                    if (p2) a2 = __ldg(reinterpret_cast<const float4*>(rowp + 2 * C_TOT));
                    if (p3) a3 = __ldg(reinterpret_cast<const float4*>(rowp + 3 * C_TOT));
                    m = fmax4(m, a0);
                    if (p1) m = fmax4(m, a1);
                    if (p2) m = fmax4(m, a2);
                    if (p3) m = fmax4(m, a3);
                    rowp += WDIM * C_TOT;
                }
            } else {
                // Fallback (never hit with this data shape, kept for safety).
                for (int h = hs; h < he; ++h) {
                    const float* q = rowp;
                    for (int w = 0; w < ww; ++w) {
                        m = fmax4(m, __ldg(reinterpret_cast<const float4*>(q)));
                        q += C_TOT;
                    }
                    rowp += WDIM * C_TOT;
                }
            }
        } else {
            m = make_float4(0.f, 0.f, 0.f, 0.f);
        }

        int cl = lane * 4;
        s_res[(cl + 0) * NB0 + bl] = m.x;
        s_res[(cl + 1) * NB0 + bl] = m.y;
        s_res[(cl + 2) * NB0 + bl] = m.z;
        s_res[(cl + 3) * NB0 + bl] = m.w;
    }
    __syncthreads();

    // --- coalesced staged write: out[n][half*128 + c][bin0 + j] ---
    float* obase = out + (size_t)n * (C_TOT * NBINS)
                       + (size_t)half * (CH * NBINS) + bin0;
    if (grp == 0) write_out<NB0>(obase, s_res, tid);
    else          write_out<NB1>(obase, s_res, tid);
}

extern "C" void kernel_launch(void* const* d_in, const int* in_sizes, int n_in,
                              void* d_out, int out_size) {
    const float* x    = (const float*)d_in[0];   // [B,256,50,50]
    const float* rois = (const float*)d_in[1];   // [N,5]
    float* out = (float*)d_out;                  // [N,256,7,7]

    const int N = in_sizes[1] / 5;
    const int B = in_sizes[0] / (C_TOT * HW);

    dim3 tgrid((HW + 31) / 32, C_TOT / 32, B);
    dim3 tblock(32, 8);
    transpose_in_kernel<<<tgrid, tblock>>>(x);

    dim3 ggrid(N, C_TOT / CH, 2);                // (128, 2, 2) = 512 blocks
    roi_gather_kernel<<<ggrid, GTHREADS>>>(rois, out, N);
}